// round 4
// baseline (speedup 1.0000x reference)
#include <cuda_runtime.h>
#include <cuda_bf16.h>
#include <math.h>
#include <stdint.h>

// LSTM T=512, B=64, I=H=512 on GB300 (sm_103a via compute_103 -> HMMA path).
// Persistent 128-CTA x 512-thread cooperative kernel, 2 grid barriers/step.
// CTA = cg*4+kg: cg in [0,32) owns 64 gate cols, kg in [0,4) owns 256 of K=1024.
// Per step: partial gates = A(64x256) @ W(256x64) via mma.sync m16n8k16 bf16,
// 3-pass split (A_hi*W_hi + A_hi*W_lo + A_lo*W_hi, fp32 accum).
// 16 warps tiled 4M x 4N (warp tile M16xN16). Elementwise gathers coalesced.

#define T_STEPS 512
#define B_SZ    64
#define H_SZ    512
#define I_SZ    512
#define G4      2048
#define NCTA    128
#define NTHR    512
#define KG_SZ   256
#define CG_COLS 64

#define ROW_STRIDE_B 528
#define TILE_BYTES   (64 * ROW_STRIDE_B)   // 33792
#define SM_BIAS 0
#define SM_A_HI 64
#define SM_A_LO (SM_A_HI + TILE_BYTES)
#define SM_W_HI (SM_A_LO + TILE_BYTES)
#define SM_W_LO (SM_W_HI + TILE_BYTES)
#define SM_TOTAL (SM_W_LO + TILE_BYTES)    // 135232

__device__ __align__(16) __nv_bfloat16 g_x_hi[T_STEPS * B_SZ * I_SZ];
__device__ __align__(16) __nv_bfloat16 g_x_lo[T_STEPS * B_SZ * I_SZ];
__device__ __align__(16) __nv_bfloat16 g_h_hi[B_SZ * H_SZ];
__device__ __align__(16) __nv_bfloat16 g_h_lo[B_SZ * H_SZ];
__device__ float    g_part[4 * G4 * B_SZ];   // [kg][col][b]
__device__ unsigned g_bar;

__device__ __forceinline__ void grid_barrier(unsigned target) {
    __syncthreads();
    if (threadIdx.x == 0) {
        unsigned* bar = &g_bar;
        asm volatile("red.release.gpu.add.u32 [%0], 1;" :: "l"(bar) : "memory");
        unsigned v;
        do {
            asm volatile("ld.acquire.gpu.u32 %0, [%1];" : "=r"(v) : "l"(bar) : "memory");
        } while (v < target);
    }
    __syncthreads();
}

__device__ __forceinline__ float sigmoidf_fast(float x) {
    return 1.0f / (1.0f + __expf(-x));
}
__device__ __forceinline__ float tanhf_fast(float x) {
    return 2.0f / (1.0f + __expf(-2.0f * x)) - 1.0f;
}

__device__ __forceinline__ void mma_bf16(float* d, const uint32_t* a, const uint32_t* b) {
    asm volatile(
        "mma.sync.aligned.m16n8k16.row.col.f32.bf16.bf16.f32 "
        "{%0,%1,%2,%3}, {%4,%5,%6,%7}, {%8,%9}, {%0,%1,%2,%3};"
        : "+f"(d[0]), "+f"(d[1]), "+f"(d[2]), "+f"(d[3])
        : "r"(a[0]), "r"(a[1]), "r"(a[2]), "r"(a[3]), "r"(b[0]), "r"(b[1]));
}

extern "C" __global__ void __launch_bounds__(NTHR, 1)
lstm_hmma_kernel(const float* __restrict__ x,
                 const float* __restrict__ hidden0,
                 const float* __restrict__ cell0,
                 const float* __restrict__ W,
                 const float* __restrict__ bias,
                 float* __restrict__ out)
{
    extern __shared__ char smem[];
    float* sbias = (float*)(smem + SM_BIAS);

    const int tid = threadIdx.x;
    const int bid = blockIdx.x;
    const int cg  = bid >> 2;
    const int kg  = bid & 3;
    const int wid = tid >> 5;
    const int lid = tid & 31;
    const int grp = lid >> 2;     // groupID 0..7
    const int tg  = lid & 3;      // thread-in-group

    // GEMM warp tile: 4 warps along M, 4 along N; warp tile M16 x N16
    const int m_base = (wid & 3) * 16;
    const int n_base = (wid >> 2) * 16;

    // elementwise ownership (warps 0..7 only): lane = eb (coalesced g_part reads)
    const int ew  = wid;                 // valid for wid < 8
    const int ejj = ew >> 1;             // 0..3
    const int ej  = bid * 4 + ejj;
    const int eb  = (ew & 1) * 32 + lid; // 0..63

    // ---- init: W slice -> SMEM bf16 hi/lo, layout [n][k] padded ----
    {
        const float* wsrc = W + (size_t)(kg * KG_SZ) * G4 + cg * CG_COLS;
        for (int idx = tid; idx < KG_SZ * CG_COLS; idx += NTHR) {
            int n = idx & 63;
            int k = idx >> 6;
            float w = wsrc[(size_t)k * G4 + n];
            __nv_bfloat16 hi = __float2bfloat16_rn(w);
            __nv_bfloat16 lo = __float2bfloat16_rn(w - __bfloat162float(hi));
            int o = n * ROW_STRIDE_B + k * 2;
            *(__nv_bfloat16*)(smem + SM_W_HI + o) = hi;
            *(__nv_bfloat16*)(smem + SM_W_LO + o) = lo;
        }
    }
    if (tid < 16) {
        int gate = tid >> 2;
        int jj   = tid & 3;
        sbias[tid] = bias[gate * H_SZ + bid * 4 + jj];
    }
    // ---- pre-split x -> bf16 hi/lo (grid-strided) ----
    {
        const float4* x4 = (const float4*)x;
        const int n4 = T_STEPS * B_SZ * I_SZ / 4;
        for (int i = bid * NTHR + tid; i < n4; i += NCTA * NTHR) {
            float4 v = x4[i];
            __nv_bfloat16 h0 = __float2bfloat16_rn(v.x);
            __nv_bfloat16 h1 = __float2bfloat16_rn(v.y);
            __nv_bfloat16 h2 = __float2bfloat16_rn(v.z);
            __nv_bfloat16 h3 = __float2bfloat16_rn(v.w);
            __nv_bfloat162* dh = (__nv_bfloat162*)(g_x_hi + 4 * (size_t)i);
            dh[0] = __nv_bfloat162(h0, h1);
            dh[1] = __nv_bfloat162(h2, h3);
            __nv_bfloat162* dl = (__nv_bfloat162*)(g_x_lo + 4 * (size_t)i);
            dl[0] = __nv_bfloat162(__float2bfloat16_rn(v.x - __bfloat162float(h0)),
                                   __float2bfloat16_rn(v.y - __bfloat162float(h1)));
            dl[1] = __nv_bfloat162(__float2bfloat16_rn(v.z - __bfloat162float(h2)),
                                   __float2bfloat16_rn(v.w - __bfloat162float(h3)));
        }
    }
    // ---- state init (elementwise owners only) ----
    float c_state = 0.0f;
    float h_last  = 0.0f;
    if (tid < 256) {
        c_state = cell0[eb * H_SZ + ej];
        float hv = hidden0[eb * H_SZ + ej];
        __nv_bfloat16 hh = __float2bfloat16_rn(hv);
        g_h_hi[eb * H_SZ + ej] = hh;
        g_h_lo[eb * H_SZ + ej] = __float2bfloat16_rn(hv - __bfloat162float(hh));
    }

    unsigned bar_n = 1;
    grid_barrier(NCTA * bar_n); bar_n++;

    // ---- time loop ----
    for (int t = 0; t < T_STEPS; t++) {
        // stage A hi/lo: rows b=0..63, k slice [kg*256, +256)
        {
            const __nv_bfloat16* sh;
            const __nv_bfloat16* sl;
            if (kg < 2) {
                size_t off = (size_t)t * B_SZ * I_SZ + kg * KG_SZ;
                sh = g_x_hi + off;
                sl = g_x_lo + off;
            } else {
                sh = g_h_hi + (kg - 2) * KG_SZ;
                sl = g_h_lo + (kg - 2) * KG_SZ;
            }
            #pragma unroll
            for (int it = 0; it < 4; it++) {
                int idx = tid + it * NTHR;       // 0..2047
                int r   = idx >> 5;              // 0..63
                int c16 = idx & 31;              // 16B unit
                uint4 vh = *(const uint4*)(sh + (size_t)r * 512 + c16 * 8);
                uint4 vl = *(const uint4*)(sl + (size_t)r * 512 + c16 * 8);
                int o = r * ROW_STRIDE_B + c16 * 16;
                *(uint4*)(smem + SM_A_HI + o) = vh;
                *(uint4*)(smem + SM_A_LO + o) = vl;
            }
        }
        __syncthreads();

        // ---- 64x64x256 GEMM: 3-pass bf16 split, m16n8k16, warp tile M16xN16 ----
        float acc[2][4];
        #pragma unroll
        for (int i = 0; i < 2; i++) {
            acc[i][0] = 0.f; acc[i][1] = 0.f; acc[i][2] = 0.f; acc[i][3] = 0.f;
        }
        {
            const char* arow = smem + (m_base + grp) * ROW_STRIDE_B + tg * 4;
            #pragma unroll 4
            for (int ks = 0; ks < 16; ks++) {
                const int kb = ks * 32;   // byte offset of k0 within row
                uint32_t a_hi[4], a_lo[4];
                a_hi[0] = *(const uint32_t*)(arow + SM_A_HI + kb);
                a_hi[1] = *(const uint32_t*)(arow + SM_A_HI + 8 * ROW_STRIDE_B + kb);
                a_hi[2] = *(const uint32_t*)(arow + SM_A_HI + kb + 16);
                a_hi[3] = *(const uint32_t*)(arow + SM_A_HI + 8 * ROW_STRIDE_B + kb + 16);
                a_lo[0] = *(const uint32_t*)(arow + SM_A_LO + kb);
                a_lo[1] = *(const uint32_t*)(arow + SM_A_LO + 8 * ROW_STRIDE_B + kb);
                a_lo[2] = *(const uint32_t*)(arow + SM_A_LO + kb + 16);
                a_lo[3] = *(const uint32_t*)(arow + SM_A_LO + 8 * ROW_STRIDE_B + kb + 16);
                #pragma unroll
                for (int nt = 0; nt < 2; nt++) {
                    const char* brow = smem + (n_base + nt * 8 + grp) * ROW_STRIDE_B + tg * 4 + kb;
                    uint32_t b_hi[2], b_lo[2];
                    b_hi[0] = *(const uint32_t*)(brow + SM_W_HI);
                    b_hi[1] = *(const uint32_t*)(brow + SM_W_HI + 16);
                    b_lo[0] = *(const uint32_t*)(brow + SM_W_LO);
                    b_lo[1] = *(const uint32_t*)(brow + SM_W_LO + 16);
                    mma_bf16(acc[nt], a_hi, b_hi);
                    mma_bf16(acc[nt], a_hi, b_lo);
                    mma_bf16(acc[nt], a_lo, b_hi);
                }
            }
        }
        // write partials: g_part[kg][col][b]
        {
            #pragma unroll
            for (int nt = 0; nt < 2; nt++) {
                int col = cg * CG_COLS + n_base + nt * 8 + tg * 2;
                int b0  = m_base + grp;
                g_part[((size_t)kg * G4 + col)     * B_SZ + b0]     = acc[nt][0];
                g_part[((size_t)kg * G4 + col + 1) * B_SZ + b0]     = acc[nt][1];
                g_part[((size_t)kg * G4 + col)     * B_SZ + b0 + 8] = acc[nt][2];
                g_part[((size_t)kg * G4 + col + 1) * B_SZ + b0 + 8] = acc[nt][3];
            }
        }

        grid_barrier(NCTA * bar_n); bar_n++;

        // elementwise (warps 0..7): reduce 4 partials + bias, LSTM cell, emit h
        if (tid < 256) {
            float g0 = sbias[0 * 4 + ejj];
            float g1 = sbias[1 * 4 + ejj];
            float g2 = sbias[2 * 4 + ejj];
            float g3 = sbias[3 * 4 + ejj];
            #pragma unroll
            for (int kk = 0; kk < 4; kk++) {
                g0 += g_part[((size_t)kk * G4 + 0 * H_SZ + ej) * B_SZ + eb];
                g1 += g_part[((size_t)kk * G4 + 1 * H_SZ + ej) * B_SZ + eb];
                g2 += g_part[((size_t)kk * G4 + 2 * H_SZ + ej) * B_SZ + eb];
                g3 += g_part[((size_t)kk * G4 + 3 * H_SZ + ej) * B_SZ + eb];
            }
            float f  = sigmoidf_fast(g0);
            float ii = sigmoidf_fast(g1);
            float cd = tanhf_fast(g2);
            float o  = sigmoidf_fast(g3);
            c_state = f * c_state + ii * cd;
            float h = o * tanhf_fast(c_state);
            h_last = h;
            out[(size_t)t * (B_SZ * H_SZ) + eb * H_SZ + ej] = h;
            __nv_bfloat16 hh = __float2bfloat16_rn(h);
            g_h_hi[eb * H_SZ + ej] = hh;
            g_h_lo[eb * H_SZ + ej] = __float2bfloat16_rn(h - __bfloat162float(hh));
        }

        grid_barrier(NCTA * bar_n); bar_n++;
    }

    // final states
    if (tid < 256) {
        size_t base = (size_t)T_STEPS * B_SZ * H_SZ;
        out[base + eb * H_SZ + ej] = h_last;
        out[base + B_SZ * H_SZ + eb * H_SZ + ej] = c_state;
    }
}

extern "C" void kernel_launch(void* const* d_in, const int* in_sizes, int n_in,
                              void* d_out, int out_size)
{
    (void)in_sizes; (void)n_in; (void)out_size;
    const float* x       = (const float*)d_in[0];
    const float* hidden0 = (const float*)d_in[1];
    const float* cell0   = (const float*)d_in[2];
    const float* W       = (const float*)d_in[3];
    const float* bias    = (const float*)d_in[4];
    float* out = (float*)d_out;

    void* bar_addr = nullptr;
    cudaGetSymbolAddress(&bar_addr, g_bar);
    cudaMemsetAsync(bar_addr, 0, sizeof(unsigned));

    cudaFuncSetAttribute(lstm_hmma_kernel,
                         cudaFuncAttributeMaxDynamicSharedMemorySize, SM_TOTAL);

    lstm_hmma_kernel<<<NCTA, NTHR, SM_TOTAL>>>(x, hidden0, cell0, W, bias, out);
}